// round 11
// baseline (speedup 1.0000x reference)
#include <cuda_runtime.h>
#include <cuda_bf16.h>
#include <math.h>

#define B_ 8
#define C_ 64
#define H_ 128
#define W_ 128
#define HS 256
#define WS 256

__device__ __forceinline__ unsigned long long pack2(float lo, float hi)
{
    unsigned long long r;
    asm("mov.b64 %0, {%1, %2};" : "=l"(r) : "f"(lo), "f"(hi));
    return r;
}
__device__ __forceinline__ float2 unpack2(unsigned long long v)
{
    float lo, hi;
    asm("mov.b64 {%0, %1}, %2;" : "=f"(lo), "=f"(hi) : "l"(v));
    return make_float2(lo, hi);
}
#define FMA2(acc, ww, tt) \
    asm("fma.rn.f32x2 %0, %1, %2, %0;" : "+l"(acc) : "l"(ww), "l"(tt))

__device__ __forceinline__ float4 ldg4_or_zero(const float* p, bool pred)
{
    if (pred) return *(const float4*)p;
    return make_float4(0.f, 0.f, 0.f, 0.f);
}

// ---------------------------------------------------------------------------
// Fused mean -> weights -> CARAFE.
// Block = 128 thr = 4 warps = 2 low-res rows x 2 hi-res sub-rows.
// Outer loop over pixel pairs pp={0,1}: 18 packed weight regs live at a time,
// then a 64-channel loop with 3x LDG.128 + shuffles + 18 FMA2 + 1 STG.128.
// ~95 live regs -> launch_bounds(128,5): 5 CTAs/SM, 20 warps, no spills.
// ---------------------------------------------------------------------------
__global__ void __launch_bounds__(128, 5) carafe_full_kernel(
    const float* __restrict__ x,
    const float* __restrict__ w_off,
    const float* __restrict__ b_off,
    float* __restrict__ out)
{
    __shared__ float sm[4][132];       // mean rows y0-1..y0+2, halo col offset 1
    __shared__ float sc0[2][2][9];     // collapsed 5x5 coeffs, offset-ch 0
    __shared__ float sc1[2][2][9];     // offset-ch 1
    __shared__ float sbias[2];

    if (threadIdx.x < 4) {
        int ir = threadIdx.x >> 1, j = threadIdx.x & 1;
        float a0[9], a1[9];
#pragma unroll
        for (int k = 0; k < 9; k++) { a0[k] = 0.f; a1[k] = 0.f; }
#pragma unroll
        for (int pp = 0; pp < 5; pp++)
#pragma unroll
            for (int qq = 0; qq < 5; qq++) {
                int k = (((ir + pp - 2) >> 1) + 1) * 3 + (((j + qq - 2) >> 1) + 1);
                a0[k] += w_off[pp * 5 + qq];
                a1[k] += w_off[25 + pp * 5 + qq];
            }
#pragma unroll
        for (int k = 0; k < 9; k++) { sc0[ir][j][k] = a0[k]; sc1[ir][j][k] = a1[k]; }
    }
    if (threadIdx.x < 2) sbias[threadIdx.x] = b_off[threadIdx.x];

    int b  = blockIdx.x >> 6;
    int y0 = (blockIdx.x & 63) * 2;
    int warp = threadIdx.x >> 5;
    int lane = threadIdx.x & 31;

    // ---- Phase 1: mean of rows y0-1..y0+2, one row per warp, ILP-4 ----
    {
        int yy = y0 - 1 + warp;
        float4 a[4];
#pragma unroll
        for (int i = 0; i < 4; i++) a[i] = make_float4(0.f, 0.f, 0.f, 0.f);
        if (yy >= 0 && yy < H_) {
            const float4* px = (const float4*)(x + ((size_t)b << 20) + yy * W_) + lane;
#pragma unroll
            for (int c = 0; c < C_; c += 4) {
#pragma unroll
                for (int i = 0; i < 4; i++) {
                    float4 v = px[(size_t)(c + i) << 12];
                    a[i].x += v.x; a[i].y += v.y; a[i].z += v.z; a[i].w += v.w;
                }
            }
        }
        const float inv = 1.0f / 64.0f;
        sm[warp][1 + 4 * lane + 0] = (a[0].x + a[1].x + a[2].x + a[3].x) * inv;
        sm[warp][1 + 4 * lane + 1] = (a[0].y + a[1].y + a[2].y + a[3].y) * inv;
        sm[warp][1 + 4 * lane + 2] = (a[0].z + a[1].z + a[2].z + a[3].z) * inv;
        sm[warp][1 + 4 * lane + 3] = (a[0].w + a[1].w + a[2].w + a[3].w) * inv;
        if (lane == 0)  sm[warp][0]   = 0.f;
        if (lane == 31) sm[warp][129] = 0.f;
    }
    __syncthreads();

    int dy = warp & 1;
    int ir = warp >> 1;
    int y = y0 + dy;
    bool hasN = (y > 0), hasS = (y < H_ - 1);
    bool z0 = (lane == 0), z31 = (lane == 31);
    const unsigned msk = 0xffffffffu;

    const float* xrow = x + ((size_t)b << 20) + y * W_ + 4 * lane;
    float* obase = out + (size_t)(b * C_) * (HS * WS)
                       + (size_t)(2 * y + ir) * WS + 8 * lane;

    // ---- Outer loop over pixel pairs: weights (18 ull) + channel loop ----
#pragma unroll 1
    for (int pp = 0; pp < 2; pp++) {
        // weights for pixels 4*lane + 2*pp + {0,1}, sub-row ir, both sub-cols
        unsigned long long wp[2][9];   // [j][k] = {w_pixA, w_pixB}
        {
            float lo[18];
#pragma unroll
            for (int ph = 0; ph < 2; ph++) {
                int p = 2 * pp + ph;
                float m0[9];
#pragma unroll
                for (int r = 0; r < 3; r++)
#pragma unroll
                    for (int cc = 0; cc < 3; cc++)
                        m0[r * 3 + cc] = sm[dy + r][4 * lane + p + cc];
                float g9[9];
                float mc = m0[4];
#pragma unroll
                for (int k = 0; k < 9; k++) {
                    float d = m0[k] - mc;
                    g9[k] = __fdividef(1.0f, d * d + 1.0f);
                }
#pragma unroll
                for (int j = 0; j < 2; j++) {
                    float o0 = 0.f, o1 = 0.f;
#pragma unroll
                    for (int k = 0; k < 9; k++) {
                        o0 = fmaf(m0[k], sc0[ir][j][k], o0);
                        o1 = fmaf(m0[k], sc1[ir][j][k], o1);
                    }
                    float s0 = (ir ? 0.25f : -0.25f) + 0.25f * tanhf(o0 + sbias[0]);
                    float s1 = (j  ? 0.25f : -0.25f) + 0.25f * tanhf(o1 + sbias[1]);
                    float lv[9];
                    float sum = 0.f;
#pragma unroll
                    for (int k = 0; k < 9; k++) {
                        float d0 = s0 - (float)(k / 3 - 1);
                        float d1 = s1 - (float)(k % 3 - 1);
                        float ker = __fdividef(1.0f, d0 * d0 + d1 * d1 + 0.5f);
                        lv[k] = __expf(g9[k] * ker);   // arg in (0,2]
                        sum += lv[k];
                    }
                    float sinv = __fdividef(1.0f, sum);
                    if (ph == 0) {
#pragma unroll
                        for (int k = 0; k < 9; k++) lo[j * 9 + k] = lv[k] * sinv;
                    } else {
#pragma unroll
                        for (int k = 0; k < 9; k++)
                            wp[j][k] = pack2(lo[j * 9 + k], lv[k] * sinv);
                    }
                }
            }
        }

        // channel loop for this pixel pair
        const float* px = xrow;
        float* ob = obase + 4 * pp;

#pragma unroll 1
        for (int c = 0; c < C_; c++) {
            float4 q0 = ldg4_or_zero(px - W_, hasN);
            float4 q1 = *(const float4*)px;
            float4 q2 = ldg4_or_zero(px + W_, hasS);

            float lf0 = __shfl_up_sync(msk, q0.w, 1);
            float lf1 = __shfl_up_sync(msk, q1.w, 1);
            float lf2 = __shfl_up_sync(msk, q2.w, 1);
            float rt0 = __shfl_down_sync(msk, q0.x, 1);
            float rt1 = __shfl_down_sync(msk, q1.x, 1);
            float rt2 = __shfl_down_sync(msk, q2.x, 1);
            if (z0)  { lf0 = 0.f; lf1 = 0.f; lf2 = 0.f; }
            if (z31) { rt0 = 0.f; rt1 = 0.f; rt2 = 0.f; }

            // taps vv[r][0..5] = {lf, q.x,q.y,q.z,q.w, rt}; this pair uses
            // indices 2pp..2pp+3 -> packed tp[r][cc] = {vv[2pp+cc], vv[2pp+cc+1]}
            float vv0[6] = {lf0, q0.x, q0.y, q0.z, q0.w, rt0};
            float vv1[6] = {lf1, q1.x, q1.y, q1.z, q1.w, rt1};
            float vv2[6] = {lf2, q2.x, q2.y, q2.z, q2.w, rt2};

            unsigned long long acc0 = 0ull, acc1 = 0ull;
#pragma unroll
            for (int cc = 0; cc < 3; cc++) {
                unsigned long long t0 = pack2(vv0[2 * pp + cc], vv0[2 * pp + cc + 1]);
                unsigned long long t1 = pack2(vv1[2 * pp + cc], vv1[2 * pp + cc + 1]);
                unsigned long long t2 = pack2(vv2[2 * pp + cc], vv2[2 * pp + cc + 1]);
                FMA2(acc0, wp[0][0 + cc], t0);
                FMA2(acc1, wp[1][0 + cc], t0);
                FMA2(acc0, wp[0][3 + cc], t1);
                FMA2(acc1, wp[1][3 + cc], t1);
                FMA2(acc0, wp[0][6 + cc], t2);
                FMA2(acc1, wp[1][6 + cc], t2);
            }

            float2 a0 = unpack2(acc0);   // sub-col 0, pixels {A,B}
            float2 a1 = unpack2(acc1);   // sub-col 1, pixels {A,B}
            __stcs((float4*)ob, make_float4(a0.x, a1.x, a0.y, a1.y));

            px += 16384;
            ob += (size_t)HS * WS;
        }
    }
}

extern "C" void kernel_launch(void* const* d_in, const int* in_sizes, int n_in,
                              void* d_out, int out_size)
{
    const float* x     = (const float*)d_in[0];   // [8,64,128,128]
    const float* w_off = (const float*)d_in[1];   // [2,1,5,5]
    const float* b_off = (const float*)d_in[2];   // [2]
    float* out = (float*)d_out;                   // [8,64,256,256]

    carafe_full_kernel<<<B_ * H_ / 2, 128>>>(x, w_off, b_off, out);
}

// round 12
// speedup vs baseline: 2.1517x; 2.1517x over previous
#include <cuda_runtime.h>
#include <cuda_bf16.h>
#include <math.h>

#define B_ 8
#define C_ 64
#define H_ 128
#define W_ 128
#define HS 256
#define WS 256

__device__ __forceinline__ unsigned long long pack2(float lo, float hi)
{
    unsigned long long r;
    asm("mov.b64 %0, {%1, %2};" : "=l"(r) : "f"(lo), "f"(hi));
    return r;
}
__device__ __forceinline__ float2 unpack2(unsigned long long v)
{
    float lo, hi;
    asm("mov.b64 {%0, %1}, %2;" : "=f"(lo), "=f"(hi) : "l"(v));
    return make_float2(lo, hi);
}
#define FMA2(acc, ww, tt) \
    asm("fma.rn.f32x2 %0, %1, %2, %0;" : "+l"(acc) : "l"(ww), "l"(tt))

// ---------------------------------------------------------------------------
// Fused mean -> weights -> CARAFE.
// Block = 256 thr = 8 warps = (col-half h) x (row dy) x (sub-row ir),
// covering low-res rows y0, y0+1. Lane owns 2 pixels (X, X+1), X = 64h+2lane.
// 18 packed weight regs/thread; one contiguous STG.128 per channel per lane.
// ---------------------------------------------------------------------------
__global__ void __launch_bounds__(256, 2) carafe_full_kernel(
    const float* __restrict__ x,
    const float* __restrict__ w_off,
    const float* __restrict__ b_off,
    float* __restrict__ out)
{
    __shared__ float smA[4][132];      // rows y0-1..y0+2, channel half 0 sums
    __shared__ float smB[4][132];      // channel half 1 sums
    __shared__ float sc0[2][2][9];     // collapsed 5x5 conv coeffs, offset-ch 0
    __shared__ float sc1[2][2][9];     // offset-ch 1
    __shared__ float sbias[2];

    if (threadIdx.x < 4) {
        int ir = threadIdx.x >> 1, j = threadIdx.x & 1;
        float a0[9], a1[9];
#pragma unroll
        for (int k = 0; k < 9; k++) { a0[k] = 0.f; a1[k] = 0.f; }
#pragma unroll
        for (int pp = 0; pp < 5; pp++)
#pragma unroll
            for (int qq = 0; qq < 5; qq++) {
                int k = (((ir + pp - 2) >> 1) + 1) * 3 + (((j + qq - 2) >> 1) + 1);
                a0[k] += w_off[pp * 5 + qq];
                a1[k] += w_off[25 + pp * 5 + qq];
            }
#pragma unroll
        for (int k = 0; k < 9; k++) { sc0[ir][j][k] = a0[k]; sc1[ir][j][k] = a1[k]; }
    }
    if (threadIdx.x < 2) sbias[threadIdx.x] = b_off[threadIdx.x];

    int b  = blockIdx.x >> 6;
    int y0 = (blockIdx.x & 63) * 2;
    int warp = threadIdx.x >> 5;       // 0..7
    int lane = threadIdx.x & 31;

    // ---- Phase 1: warp (r, hc) sums 32 channels of row y0-1+r ----
    {
        int r  = warp >> 1;            // 0..3
        int hc = warp & 1;             // channel half
        int yy = y0 - 1 + r;
        float4 a[4];
#pragma unroll
        for (int i = 0; i < 4; i++) a[i] = make_float4(0.f, 0.f, 0.f, 0.f);
        if (yy >= 0 && yy < H_) {
            const float4* px = (const float4*)(x + ((size_t)b << 20)
                                + ((size_t)(hc * 32) << 14) + yy * W_) + lane;
#pragma unroll
            for (int c = 0; c < 32; c += 4) {
#pragma unroll
                for (int i = 0; i < 4; i++) {
                    float4 v = px[(size_t)(c + i) << 12];
                    a[i].x += v.x; a[i].y += v.y; a[i].z += v.z; a[i].w += v.w;
                }
            }
        }
        float* dst = hc ? &smB[r][0] : &smA[r][0];
        dst[1 + 4 * lane + 0] = a[0].x + a[1].x + a[2].x + a[3].x;
        dst[1 + 4 * lane + 1] = a[0].y + a[1].y + a[2].y + a[3].y;
        dst[1 + 4 * lane + 2] = a[0].z + a[1].z + a[2].z + a[3].z;
        dst[1 + 4 * lane + 3] = a[0].w + a[1].w + a[2].w + a[3].w;
        if (lane == 0)  dst[0]   = 0.f;
        if (lane == 31) dst[129] = 0.f;
    }
    __syncthreads();

    // ---- decode roles ----
    int h  = warp & 1;                 // column half
    int dy = (warp >> 1) & 1;          // low-res row within block
    int ir = warp >> 2;                // hi-res sub-row
    int y = y0 + dy;
    int X = 64 * h + 2 * lane;         // first pixel of this lane
    bool hasN = (y > 0), hasS = (y < H_ - 1);

    // ---- Phase 2: weights for pixels X, X+1 (sub-row ir, both sub-cols) ----
    unsigned long long wp[2][9];       // [j][k] = {w_pixA, w_pixB}
    {
        float lo[18];
#pragma unroll
        for (int ph = 0; ph < 2; ph++) {
            float m0[9];
#pragma unroll
            for (int r = 0; r < 3; r++)
#pragma unroll
                for (int cc = 0; cc < 3; cc++) {
                    int idx = X + ph + cc;            // smem col (X+ph-1+cc)+1
                    m0[r * 3 + cc] =
                        (smA[dy + r][idx] + smB[dy + r][idx]) * (1.0f / 64.0f);
                }
            float g9[9];
            float mc = m0[4];
#pragma unroll
            for (int k = 0; k < 9; k++) {
                float d = m0[k] - mc;
                g9[k] = __fdividef(1.0f, d * d + 1.0f);
            }
#pragma unroll
            for (int j = 0; j < 2; j++) {
                float o0 = 0.f, o1 = 0.f;
#pragma unroll
                for (int k = 0; k < 9; k++) {
                    o0 = fmaf(m0[k], sc0[ir][j][k], o0);
                    o1 = fmaf(m0[k], sc1[ir][j][k], o1);
                }
                float s0 = (ir ? 0.25f : -0.25f) + 0.25f * tanhf(o0 + sbias[0]);
                float s1 = (j  ? 0.25f : -0.25f) + 0.25f * tanhf(o1 + sbias[1]);
                float lv[9];
                float sum = 0.f;
#pragma unroll
                for (int k = 0; k < 9; k++) {
                    float d0 = s0 - (float)(k / 3 - 1);
                    float d1 = s1 - (float)(k % 3 - 1);
                    float ker = __fdividef(1.0f, d0 * d0 + d1 * d1 + 0.5f);
                    lv[k] = __expf(g9[k] * ker);   // arg in (0,2]: no max-sub
                    sum += lv[k];
                }
                float sinv = __fdividef(1.0f, sum);
                if (ph == 0) {
#pragma unroll
                    for (int k = 0; k < 9; k++) lo[j * 9 + k] = lv[k] * sinv;
                } else {
#pragma unroll
                    for (int k = 0; k < 9; k++)
                        wp[j][k] = pack2(lo[j * 9 + k], lv[k] * sinv);
                }
            }
        }
    }

    // ---- Phase 3: CARAFE channel loop ----
    const float* px = x + ((size_t)b << 20) + y * W_ + X;
    float* ob = out + (size_t)(b * C_) * (HS * WS)
                    + (size_t)(2 * y + ir) * WS + 2 * X;
    const unsigned msk = 0xffffffffu;
    bool z0 = (lane == 0), z31 = (lane == 31);

#pragma unroll 1
    for (int c = 0; c < C_; c++) {
        float2 q0 = hasN ? *(const float2*)(px - W_) : make_float2(0.f, 0.f);
        float2 q1 = *(const float2*)px;
        float2 q2 = hasS ? *(const float2*)(px + W_) : make_float2(0.f, 0.f);

        float lf0 = __shfl_up_sync(msk, q0.y, 1);
        float lf1 = __shfl_up_sync(msk, q1.y, 1);
        float lf2 = __shfl_up_sync(msk, q2.y, 1);
        float rt0 = __shfl_down_sync(msk, q0.x, 1);
        float rt1 = __shfl_down_sync(msk, q1.x, 1);
        float rt2 = __shfl_down_sync(msk, q2.x, 1);

        if (h) {                        // warp-uniform branch
            if (z0) {                   // seam: pixel 63 (interior load)
                lf0 = hasN ? px[-1 - W_] : 0.f;
                lf1 = px[-1];
                lf2 = hasS ? px[-1 + W_] : 0.f;
            }
            if (z31) { rt0 = 0.f; rt1 = 0.f; rt2 = 0.f; }   // col 128 -> pad
        } else {
            if (z0)  { lf0 = 0.f; lf1 = 0.f; lf2 = 0.f; }   // col -1 -> pad
            if (z31) {                  // seam: pixel 64 (interior load)
                rt0 = hasN ? px[2 - W_] : 0.f;
                rt1 = px[2];
                rt2 = hasS ? px[2 + W_] : 0.f;
            }
        }

        // packed taps: tp[r][cc] = {tap_pixA(cc-1), tap_pixB(cc-1)}
        unsigned long long t00 = pack2(lf0, q0.x);
        unsigned long long t01 = pack2(q0.x, q0.y);
        unsigned long long t02 = pack2(q0.y, rt0);
        unsigned long long t10 = pack2(lf1, q1.x);
        unsigned long long t11 = pack2(q1.x, q1.y);
        unsigned long long t12 = pack2(q1.y, rt1);
        unsigned long long t20 = pack2(lf2, q2.x);
        unsigned long long t21 = pack2(q2.x, q2.y);
        unsigned long long t22 = pack2(q2.y, rt2);

        unsigned long long acc0 = 0ull, acc1 = 0ull;
        FMA2(acc0, wp[0][0], t00);  FMA2(acc1, wp[1][0], t00);
        FMA2(acc0, wp[0][1], t01);  FMA2(acc1, wp[1][1], t01);
        FMA2(acc0, wp[0][2], t02);  FMA2(acc1, wp[1][2], t02);
        FMA2(acc0, wp[0][3], t10);  FMA2(acc1, wp[1][3], t10);
        FMA2(acc0, wp[0][4], t11);  FMA2(acc1, wp[1][4], t11);
        FMA2(acc0, wp[0][5], t12);  FMA2(acc1, wp[1][5], t12);
        FMA2(acc0, wp[0][6], t20);  FMA2(acc1, wp[1][6], t20);
        FMA2(acc0, wp[0][7], t21);  FMA2(acc1, wp[1][7], t21);
        FMA2(acc0, wp[0][8], t22);  FMA2(acc1, wp[1][8], t22);

        float2 a0 = unpack2(acc0);     // sub-col 0: {pixA, pixB}
        float2 a1 = unpack2(acc1);     // sub-col 1: {pixA, pixB}
        __stcs((float4*)ob, make_float4(a0.x, a1.x, a0.y, a1.y));

        px += 16384;
        ob += (size_t)HS * WS;
    }
}

extern "C" void kernel_launch(void* const* d_in, const int* in_sizes, int n_in,
                              void* d_out, int out_size)
{
    const float* x     = (const float*)d_in[0];   // [8,64,128,128]
    const float* w_off = (const float*)d_in[1];   // [2,1,5,5]
    const float* b_off = (const float*)d_in[2];   // [2]
    float* out = (float*)d_out;                   // [8,64,256,256]

    carafe_full_kernel<<<B_ * H_ / 2, 256>>>(x, w_off, b_off, out);
}

// round 13
// speedup vs baseline: 2.9600x; 1.3756x over previous
#include <cuda_runtime.h>
#include <cuda_bf16.h>
#include <math.h>

#define B_ 8
#define C_ 64
#define H_ 128
#define W_ 128
#define HS 256
#define WS 256

__device__ __forceinline__ unsigned long long pack2(float lo, float hi)
{
    unsigned long long r;
    asm("mov.b64 %0, {%1, %2};" : "=l"(r) : "f"(lo), "f"(hi));
    return r;
}
__device__ __forceinline__ float2 unpack2(unsigned long long v)
{
    float lo, hi;
    asm("mov.b64 {%0, %1}, %2;" : "=f"(lo), "=f"(hi) : "l"(v));
    return make_float2(lo, hi);
}
#define FMA2(acc, ww, tt) \
    asm("fma.rn.f32x2 %0, %1, %2, %0;" : "+l"(acc) : "l"(ww), "l"(tt))

__device__ __forceinline__ void cp_async16(unsigned dst, const float* src)
{
    asm volatile("cp.async.ca.shared.global [%0], [%1], 16;"
                 :: "r"(dst), "l"(src) : "memory");
}
__device__ __forceinline__ void cp_commit()
{
    asm volatile("cp.async.commit_group;" ::: "memory");
}

// ---------------------------------------------------------------------------
// Fused mean -> weights -> CARAFE (R8 structure) + warp-private cp.async
// double-buffered staging of the 3 x-rows per channel.
// Block = 128 thr = 4 warps = 2 low-res rows x 2 hi-res sub-rows.
// Lane owns 4 pixels; per channel: 3 cp.async(16B, lane-local) prefetch 2
// ahead, 3 LDS.128 of the lane's own chunks, shuffles for halos, 36 FMA2,
// 2 contiguous STG.128. No block/warp syncs in the loop.
// ---------------------------------------------------------------------------
__global__ void __launch_bounds__(128, 4) carafe_full_kernel(
    const float* __restrict__ x,
    const float* __restrict__ w_off,
    const float* __restrict__ b_off,
    float* __restrict__ out)
{
    __shared__ float sm[4][132];
    __shared__ float sc0[2][2][9];
    __shared__ float sc1[2][2][9];
    __shared__ float sbias[2];
    __shared__ __align__(16) float stage[4][2][3][128];   // warp, buf, row, col

    if (threadIdx.x < 4) {
        int ir = threadIdx.x >> 1, j = threadIdx.x & 1;
        float a0[9], a1[9];
#pragma unroll
        for (int k = 0; k < 9; k++) { a0[k] = 0.f; a1[k] = 0.f; }
#pragma unroll
        for (int pp = 0; pp < 5; pp++)
#pragma unroll
            for (int qq = 0; qq < 5; qq++) {
                int k = (((ir + pp - 2) >> 1) + 1) * 3 + (((j + qq - 2) >> 1) + 1);
                a0[k] += w_off[pp * 5 + qq];
                a1[k] += w_off[25 + pp * 5 + qq];
            }
#pragma unroll
        for (int k = 0; k < 9; k++) { sc0[ir][j][k] = a0[k]; sc1[ir][j][k] = a1[k]; }
    }
    if (threadIdx.x < 2) sbias[threadIdx.x] = b_off[threadIdx.x];

    int b  = blockIdx.x >> 6;
    int y0 = (blockIdx.x & 63) * 2;
    int warp = threadIdx.x >> 5;
    int lane = threadIdx.x & 31;

    // ---- Phase 1: mean of rows y0-1..y0+2, one row per warp, ILP-4 ----
    {
        int yy = y0 - 1 + warp;
        float4 a[4];
#pragma unroll
        for (int i = 0; i < 4; i++) a[i] = make_float4(0.f, 0.f, 0.f, 0.f);
        if (yy >= 0 && yy < H_) {
            const float4* px = (const float4*)(x + ((size_t)b << 20) + yy * W_) + lane;
#pragma unroll
            for (int c = 0; c < C_; c += 4) {
#pragma unroll
                for (int i = 0; i < 4; i++) {
                    float4 v = px[(size_t)(c + i) << 12];
                    a[i].x += v.x; a[i].y += v.y; a[i].z += v.z; a[i].w += v.w;
                }
            }
        }
        const float inv = 1.0f / 64.0f;
        sm[warp][1 + 4 * lane + 0] = (a[0].x + a[1].x + a[2].x + a[3].x) * inv;
        sm[warp][1 + 4 * lane + 1] = (a[0].y + a[1].y + a[2].y + a[3].y) * inv;
        sm[warp][1 + 4 * lane + 2] = (a[0].z + a[1].z + a[2].z + a[3].z) * inv;
        sm[warp][1 + 4 * lane + 3] = (a[0].w + a[1].w + a[2].w + a[3].w) * inv;
        if (lane == 0)  sm[warp][0]   = 0.f;
        if (lane == 31) sm[warp][129] = 0.f;
    }
    __syncthreads();

    int dy = warp & 1;
    int ir = warp >> 1;
    int y = y0 + dy;
    bool hasN = (y > 0), hasS = (y < H_ - 1);

    // ---- Phase 2: weights (identical to R8) ----
    unsigned long long wp[4][9];   // [pp*2+j][k] = {w_pix2pp, w_pix2pp+1}
    {
        float lo[18];
#pragma unroll
        for (int p = 0; p < 4; p++) {
            float m0[9];
#pragma unroll
            for (int r = 0; r < 3; r++)
#pragma unroll
                for (int cc = 0; cc < 3; cc++)
                    m0[r * 3 + cc] = sm[dy + r][4 * lane + p + cc];
            float g9[9];
            float mc = m0[4];
#pragma unroll
            for (int k = 0; k < 9; k++) {
                float d = m0[k] - mc;
                g9[k] = __fdividef(1.0f, d * d + 1.0f);
            }
            float cur[18];
#pragma unroll
            for (int j = 0; j < 2; j++) {
                float o0 = 0.f, o1 = 0.f;
#pragma unroll
                for (int k = 0; k < 9; k++) {
                    o0 = fmaf(m0[k], sc0[ir][j][k], o0);
                    o1 = fmaf(m0[k], sc1[ir][j][k], o1);
                }
                float s0 = (ir ? 0.25f : -0.25f) + 0.25f * tanhf(o0 + sbias[0]);
                float s1 = (j  ? 0.25f : -0.25f) + 0.25f * tanhf(o1 + sbias[1]);
                float lv[9];
                float sum = 0.f;
#pragma unroll
                for (int k = 0; k < 9; k++) {
                    float d0 = s0 - (float)(k / 3 - 1);
                    float d1 = s1 - (float)(k % 3 - 1);
                    float ker = __fdividef(1.0f, d0 * d0 + d1 * d1 + 0.5f);
                    lv[k] = __expf(g9[k] * ker);
                    sum += lv[k];
                }
                float sinv = __fdividef(1.0f, sum);
#pragma unroll
                for (int k = 0; k < 9; k++) cur[j * 9 + k] = lv[k] * sinv;
            }
            if ((p & 1) == 0) {
#pragma unroll
                for (int t = 0; t < 18; t++) lo[t] = cur[t];
            } else {
#pragma unroll
                for (int j = 0; j < 2; j++)
#pragma unroll
                    for (int k = 0; k < 9; k++)
                        wp[(p >> 1) * 2 + j][k] = pack2(lo[j * 9 + k], cur[j * 9 + k]);
            }
        }
    }

    // ---- Phase 3: cp.async double-buffered channel loop ----
    const float* px = x + ((size_t)b << 20) + y * W_ + 4 * lane;
    float* ob = out + (size_t)(b * C_) * (HS * WS)
                    + (size_t)(2 * y + ir) * WS + 8 * lane;

    float* sread = &stage[warp][0][0][4 * lane];     // lane's own chunks
    unsigned sdst = (unsigned)__cvta_generic_to_shared(sread);
    // float strides: buf = 384 floats (1536B), row = 128 floats (512B)

    // pre-zero boundary rows (lane-local chunks, both buffers)
    if (!hasN) {
        *(float4*)(sread + 0)   = make_float4(0.f, 0.f, 0.f, 0.f);
        *(float4*)(sread + 384) = make_float4(0.f, 0.f, 0.f, 0.f);
    }
    if (!hasS) {
        *(float4*)(sread + 256) = make_float4(0.f, 0.f, 0.f, 0.f);
        *(float4*)(sread + 640) = make_float4(0.f, 0.f, 0.f, 0.f);
    }

    // prologue: prefetch channels 0 (buf0) and 1 (buf1)
    {
        const float* p0 = px;
        if (hasN) cp_async16(sdst + 0,    p0 - W_);
        cp_async16(sdst + 512,  p0);
        if (hasS) cp_async16(sdst + 1024, p0 + W_);
        cp_commit();
        const float* p1 = px + 16384;
        if (hasN) cp_async16(sdst + 1536 + 0,    p1 - W_);
        cp_async16(sdst + 1536 + 512,  p1);
        if (hasS) cp_async16(sdst + 1536 + 1024, p1 + W_);
        cp_commit();
    }

    const float* pfetch = px + 2 * 16384;
    const unsigned msk = 0xffffffffu;
    bool z0 = (lane == 0), z31 = (lane == 31);

#pragma unroll 1
    for (int c = 0; c < C_; c++) {
        if (c < C_ - 1) asm volatile("cp.async.wait_group 1;" ::: "memory");
        else            asm volatile("cp.async.wait_group 0;" ::: "memory");

        int p = c & 1;
        float4 q0 = *(const float4*)(sread + p * 384 + 0);
        float4 q1 = *(const float4*)(sread + p * 384 + 128);
        float4 q2 = *(const float4*)(sread + p * 384 + 256);

        // refill this buffer with channel c+2 (lane-local chunks already read)
        if (c + 2 < C_) {
            unsigned d = sdst + (unsigned)(p * 1536);
            if (hasN) cp_async16(d + 0,    pfetch - W_);
            cp_async16(d + 512,  pfetch);
            if (hasS) cp_async16(d + 1024, pfetch + W_);
            cp_commit();
            pfetch += 16384;
        }

        float lf0 = __shfl_up_sync(msk, q0.w, 1);
        float lf1 = __shfl_up_sync(msk, q1.w, 1);
        float lf2 = __shfl_up_sync(msk, q2.w, 1);
        float rt0 = __shfl_down_sync(msk, q0.x, 1);
        float rt1 = __shfl_down_sync(msk, q1.x, 1);
        float rt2 = __shfl_down_sync(msk, q2.x, 1);
        if (z0)  { lf0 = 0.f; lf1 = 0.f; lf2 = 0.f; }
        if (z31) { rt0 = 0.f; rt1 = 0.f; rt2 = 0.f; }

        unsigned long long acc00 = 0ull, acc01 = 0ull, acc10 = 0ull, acc11 = 0ull;
        // row 0
        {
            unsigned long long t0 = pack2(lf0, q0.x), t1 = pack2(q0.x, q0.y);
            unsigned long long t2 = pack2(q0.y, q0.z), t3 = pack2(q0.z, q0.w);
            unsigned long long t4 = pack2(q0.w, rt0);
            FMA2(acc00, wp[0][0], t0); FMA2(acc01, wp[1][0], t0);
            FMA2(acc00, wp[0][1], t1); FMA2(acc01, wp[1][1], t1);
            FMA2(acc00, wp[0][2], t2); FMA2(acc01, wp[1][2], t2);
            FMA2(acc10, wp[2][0], t2); FMA2(acc11, wp[3][0], t2);
            FMA2(acc10, wp[2][1], t3); FMA2(acc11, wp[3][1], t3);
            FMA2(acc10, wp[2][2], t4); FMA2(acc11, wp[3][2], t4);
        }
        // row 1
        {
            unsigned long long t0 = pack2(lf1, q1.x), t1 = pack2(q1.x, q1.y);
            unsigned long long t2 = pack2(q1.y, q1.z), t3 = pack2(q1.z, q1.w);
            unsigned long long t4 = pack2(q1.w, rt1);
            FMA2(acc00, wp[0][3], t0); FMA2(acc01, wp[1][3], t0);
            FMA2(acc00, wp[0][4], t1); FMA2(acc01, wp[1][4], t1);
            FMA2(acc00, wp[0][5], t2); FMA2(acc01, wp[1][5], t2);
            FMA2(acc10, wp[2][3], t2); FMA2(acc11, wp[3][3], t2);
            FMA2(acc10, wp[2][4], t3); FMA2(acc11, wp[3][4], t3);
            FMA2(acc10, wp[2][5], t4); FMA2(acc11, wp[3][5], t4);
        }
        // row 2
        {
            unsigned long long t0 = pack2(lf2, q2.x), t1 = pack2(q2.x, q2.y);
            unsigned long long t2 = pack2(q2.y, q2.z), t3 = pack2(q2.z, q2.w);
            unsigned long long t4 = pack2(q2.w, rt2);
            FMA2(acc00, wp[0][6], t0); FMA2(acc01, wp[1][6], t0);
            FMA2(acc00, wp[0][7], t1); FMA2(acc01, wp[1][7], t1);
            FMA2(acc00, wp[0][8], t2); FMA2(acc01, wp[1][8], t2);
            FMA2(acc10, wp[2][6], t2); FMA2(acc11, wp[3][6], t2);
            FMA2(acc10, wp[2][7], t3); FMA2(acc11, wp[3][7], t3);
            FMA2(acc10, wp[2][8], t4); FMA2(acc11, wp[3][8], t4);
        }

        float2 a00 = unpack2(acc00), a01 = unpack2(acc01);
        float2 a10 = unpack2(acc10), a11 = unpack2(acc11);

        __stcs((float4*)ob,       make_float4(a00.x, a01.x, a00.y, a01.y));
        __stcs((float4*)(ob + 4), make_float4(a10.x, a11.x, a10.y, a11.y));

        ob += (size_t)HS * WS;
    }
}

extern "C" void kernel_launch(void* const* d_in, const int* in_sizes, int n_in,
                              void* d_out, int out_size)
{
    const float* x     = (const float*)d_in[0];   // [8,64,128,128]
    const float* w_off = (const float*)d_in[1];   // [2,1,5,5]
    const float* b_off = (const float*)d_in[2];   // [2]
    float* out = (float*)d_out;                   // [8,64,256,256]

    carafe_full_kernel<<<B_ * H_ / 2, 128>>>(x, w_off, b_off, out);
}